// round 10
// baseline (speedup 1.0000x reference)
#include <cuda_runtime.h>
#include <cuda_bf16.h>
#include <math.h>

#define TT   1024
#define NBAT 64
#define KD   512
#define G3   1536

// ---- static device scratch ----
__device__ float          g_GX[(size_t)TT * NBAT * G3];
__device__ __nv_bfloat16  g_H_hi[(size_t)(TT + 1) * NBAT * KD];
__device__ __nv_bfloat16  g_H_lo[(size_t)(TT + 1) * NBAT * KD];
__device__ __nv_bfloat16  g_X_hi[(size_t)NBAT * TT * KD];
__device__ __nv_bfloat16  g_X_lo[(size_t)NBAT * TT * KD];
__device__ float          g_Whp[G3 * KD];
__device__ float          g_bpf[G3];
__device__ __nv_bfloat16  g_Mp_hi[128 * 16 * KD];
__device__ __nv_bfloat16  g_Mp_lo[128 * 16 * KD];
__device__ float          g_biasA[128 * 16];
__device__ float          g_bias0[128 * 16];
__device__ __nv_bfloat16  g_Wx_hi[G3 * KD];
__device__ __nv_bfloat16  g_Wx_lo[G3 * KD];
__device__ __nv_bfloat16  g_Wp_hi[256 * KD];
__device__ __nv_bfloat16  g_Wp_lo[256 * KD];
__device__ unsigned       g_bar;

__device__ __forceinline__ void split2(float v, __nv_bfloat16 &hi, __nv_bfloat16 &lo) {
    hi = __float2bfloat16(v);
    lo = __float2bfloat16(v - __bfloat162float(hi));
}

__device__ __forceinline__ void mma_bf16(float *d, const unsigned *a, const unsigned *b) {
    asm volatile(
        "mma.sync.aligned.m16n8k16.row.col.f32.bf16.bf16.f32 "
        "{%0,%1,%2,%3}, {%4,%5,%6,%7}, {%8,%9}, {%0,%1,%2,%3};\n"
        : "+f"(d[0]), "+f"(d[1]), "+f"(d[2]), "+f"(d[3])
        : "r"(a[0]), "r"(a[1]), "r"(a[2]), "r"(a[3]), "r"(b[0]), "r"(b[1]));
}

// ---- prep ----
__global__ void k_whp(const float *__restrict__ Wih, const float *__restrict__ Wp) {
    int idx = blockIdx.x * blockDim.x + threadIdx.x;
    if (idx >= G3 * KD) return;
    int j = idx >> 9, k = idx & 511;
    const float *wrow = Wih + (size_t)j * 768 + 512;
    float acc = 0.f;
#pragma unroll 4
    for (int p = 0; p < 256; p++) acc += wrow[p] * Wp[p * KD + k];
    g_Whp[idx] = acc;
}

__global__ void k_bpf(const float *__restrict__ Wih, const float *__restrict__ bp) {
    int j = blockIdx.x * blockDim.x + threadIdx.x;
    if (j >= G3) return;
    const float *wrow = Wih + (size_t)j * 768 + 512;
    float acc = 0.f;
    for (int p = 0; p < 256; p++) acc += wrow[p] * bp[p];
    g_bpf[j] = acc;
}

__global__ void k_pack(const float *__restrict__ Wih, const float *__restrict__ Whh,
                       const float *__restrict__ bih, const float *__restrict__ bhh,
                       const float *__restrict__ Wp) {
    int idx = blockIdx.x * blockDim.x + threadIdx.x;

    if (idx < 128 * 16 * KD) {                       // Mp + biases
        int k = idx & 511;
        int c = (idx >> 9) & 15;
        int b = idx >> 13;
        int gsel = c >> 2, jj = c & 3;
        int j = b * 4 + jj;
        float v;
        if (gsel == 0)      v = Whh[j * KD + k] + g_Whp[j * KD + k];
        else if (gsel == 1) v = Whh[(512 + j) * KD + k] + g_Whp[(512 + j) * KD + k];
        else if (gsel == 2) v = g_Whp[(1024 + j) * KD + k];
        else                v = Whh[(1024 + j) * KD + k];
        __nv_bfloat16 hi, lo;
        split2(v, hi, lo);
        g_Mp_hi[idx] = hi;
        g_Mp_lo[idx] = lo;
        if (k == 0) {
            float bb, b0;
            if (gsel == 0)      { b0 = bih[j] + bhh[j];             bb = b0 + g_bpf[j]; }
            else if (gsel == 1) { b0 = bih[512 + j] + bhh[512 + j]; bb = b0 + g_bpf[512 + j]; }
            else if (gsel == 2) { b0 = bih[1024 + j];               bb = b0 + g_bpf[1024 + j]; }
            else                { b0 = bhh[1024 + j];               bb = b0; }
            g_biasA[b * 16 + c] = bb;
            g_bias0[b * 16 + c] = b0;
        }
        return;
    }
    idx -= 128 * 16 * KD;

    if (idx < G3 * KD) {                             // Wx split
        int j = idx >> 9, k = idx & 511;
        __nv_bfloat16 hi, lo;
        split2(Wih[(size_t)j * 768 + k], hi, lo);
        g_Wx_hi[idx] = hi;
        g_Wx_lo[idx] = lo;
        return;
    }
    idx -= G3 * KD;

    if (idx < 256 * KD) {                            // Wp split
        __nv_bfloat16 hi, lo;
        split2(Wp[idx], hi, lo);
        g_Wp_hi[idx] = hi;
        g_Wp_lo[idx] = lo;
    }
}

__global__ void k_splitx(const float *__restrict__ X) {
    size_t idx = (size_t)blockIdx.x * blockDim.x + threadIdx.x;
    if (idx >= (size_t)NBAT * TT * KD) return;
    __nv_bfloat16 hi, lo;
    split2(X[idx], hi, lo);
    g_X_hi[idx] = hi;
    g_X_lo[idx] = lo;
}

__global__ void k_init() {
    int idx = blockIdx.x * blockDim.x + threadIdx.x;
    if (idx == 0) g_bar = 0u;
    if (idx < NBAT * KD) {
        g_H_hi[idx] = __float2bfloat16(0.f);
        g_H_lo[idx] = __float2bfloat16(0.f);
    }
}

// ---- GX = X @ Wx^T : grid (24,1024) x 256 threads, 64x64 tiles ----
__global__ void __launch_bounds__(256) k_gx() {
    int w = threadIdx.x >> 5, lane = threadIdx.x & 31;
    int g = lane >> 2, tg = lane & 3;
    int m0 = blockIdx.y * 64 + (w >> 1) * 16;
    int n0 = blockIdx.x * 64 + (w & 1) * 32;

    float acc[4][4];
#pragma unroll
    for (int i = 0; i < 4; i++)
#pragma unroll
        for (int q = 0; q < 4; q++) acc[i][q] = 0.f;

    const __nv_bfloat16 *a0h = g_X_hi + (size_t)(m0 + g) * KD;
    const __nv_bfloat16 *a1h = g_X_hi + (size_t)(m0 + g + 8) * KD;
    const __nv_bfloat16 *a0l = g_X_lo + (size_t)(m0 + g) * KD;
    const __nv_bfloat16 *a1l = g_X_lo + (size_t)(m0 + g + 8) * KD;

#pragma unroll 2
    for (int kc = 0; kc < KD; kc += 16) {
        unsigned ah[4], al[4];
        ah[0] = *(const unsigned *)(a0h + kc + tg * 2);
        ah[1] = *(const unsigned *)(a1h + kc + tg * 2);
        ah[2] = *(const unsigned *)(a0h + kc + tg * 2 + 8);
        ah[3] = *(const unsigned *)(a1h + kc + tg * 2 + 8);
        al[0] = *(const unsigned *)(a0l + kc + tg * 2);
        al[1] = *(const unsigned *)(a1l + kc + tg * 2);
        al[2] = *(const unsigned *)(a0l + kc + tg * 2 + 8);
        al[3] = *(const unsigned *)(a1l + kc + tg * 2 + 8);
#pragma unroll
        for (int nt = 0; nt < 4; nt++) {
            int col = n0 + nt * 8 + g;
            const __nv_bfloat16 *bh = g_Wx_hi + (size_t)col * KD + kc + tg * 2;
            const __nv_bfloat16 *bl = g_Wx_lo + (size_t)col * KD + kc + tg * 2;
            unsigned bhi[2] = { *(const unsigned *)bh, *(const unsigned *)(bh + 8) };
            unsigned blo[2] = { *(const unsigned *)bl, *(const unsigned *)(bl + 8) };
            mma_bf16(acc[nt], ah, bhi);
            mma_bf16(acc[nt], ah, blo);
            mma_bf16(acc[nt], al, bhi);
        }
    }

    // X row m = n*1024 + t  ->  GX[t][n][col]
    int ma = m0 + g, mb = m0 + g + 8;
    size_t ra = (size_t)((ma & 1023) * 64 + (ma >> 10)) * G3;
    size_t rb = (size_t)((mb & 1023) * 64 + (mb >> 10)) * G3;
#pragma unroll
    for (int nt = 0; nt < 4; nt++) {
        int col = n0 + nt * 8 + tg * 2;
        *(float2 *)(g_GX + ra + col) = make_float2(acc[nt][0], acc[nt][1]);
        *(float2 *)(g_GX + rb + col) = make_float2(acc[nt][2], acc[nt][3]);
    }
}

// ---- recurrence: persistent, 128 CTAs x 128 threads, 4 hidden units/CTA ----
__global__ void __launch_bounds__(128) k_rec() {
    __shared__ __nv_bfloat16 sWh[16][520];
    __shared__ __nv_bfloat16 sWl[16][520];
    __shared__ float sG[64][16];
    __shared__ float sBias[16], sBias0[16];

    int b = blockIdx.x;
    int tid = threadIdx.x;
    int w = tid >> 5, lane = tid & 31;
    int g = lane >> 2, tg = lane & 3;

    for (int i = tid; i < 16 * 512; i += 128) {
        int c = i >> 9, k = i & 511;
        size_t src = (size_t)b * (16 * 512) + i;
        sWh[c][k] = g_Mp_hi[src];
        sWl[c][k] = g_Mp_lo[src];
    }
    if (tid < 16) {
        sBias[tid]  = g_biasA[b * 16 + tid];
        sBias0[tid] = g_bias0[b * 16 + tid];
    }
    __syncthreads();

    int row0 = w * 16 + g;
    int row1 = row0 + 8;

    for (int t = 0; t < TT; t++) {
        const __nv_bfloat16 *Hh = g_H_hi + (size_t)t * (NBAT * KD);
        const __nv_bfloat16 *Hl = g_H_lo + (size_t)t * (NBAT * KD);
        const __nv_bfloat16 *h0h = Hh + row0 * KD;
        const __nv_bfloat16 *h1h = Hh + row1 * KD;
        const __nv_bfloat16 *h0l = Hl + row0 * KD;
        const __nv_bfloat16 *h1l = Hl + row1 * KD;

        float acc[2][4];
#pragma unroll
        for (int i = 0; i < 2; i++)
#pragma unroll
            for (int q = 0; q < 4; q++) acc[i][q] = 0.f;

#pragma unroll 4
        for (int kc = 0; kc < KD; kc += 16) {
            unsigned ah[4], al[4];
            ah[0] = *(const unsigned *)(h0h + kc + tg * 2);
            ah[1] = *(const unsigned *)(h1h + kc + tg * 2);
            ah[2] = *(const unsigned *)(h0h + kc + tg * 2 + 8);
            ah[3] = *(const unsigned *)(h1h + kc + tg * 2 + 8);
            al[0] = *(const unsigned *)(h0l + kc + tg * 2);
            al[1] = *(const unsigned *)(h1l + kc + tg * 2);
            al[2] = *(const unsigned *)(h0l + kc + tg * 2 + 8);
            al[3] = *(const unsigned *)(h1l + kc + tg * 2 + 8);
#pragma unroll
            for (int nt = 0; nt < 2; nt++) {
                int c = nt * 8 + g;
                unsigned bh[2] = { *(const unsigned *)&sWh[c][kc + tg * 2],
                                   *(const unsigned *)&sWh[c][kc + tg * 2 + 8] };
                unsigned bl[2] = { *(const unsigned *)&sWl[c][kc + tg * 2],
                                   *(const unsigned *)&sWl[c][kc + tg * 2 + 8] };
                mma_bf16(acc[nt], ah, bh);
                mma_bf16(acc[nt], ah, bl);
                mma_bf16(acc[nt], al, bh);
            }
        }

#pragma unroll
        for (int nt = 0; nt < 2; nt++) {
            int c = nt * 8 + tg * 2;
            sG[row0][c]     = acc[nt][0];
            sG[row0][c + 1] = acc[nt][1];
            sG[row1][c]     = acc[nt][2];
            sG[row1][c + 1] = acc[nt][3];
        }
        __syncthreads();

        const float *GXt = g_GX + (size_t)t * (NBAT * G3);
        const float *bias = (t == 0) ? sBias0 : sBias;
#pragma unroll
        for (int it = 0; it < 2; it++) {
            int i = tid + it * 128;
            int n = i >> 2, jj = i & 3;
            int j = b * 4 + jj;
            const float *gxr = GXt + n * G3;
            float pr = sG[n][jj]      + gxr[j]        + bias[jj];
            float pz = sG[n][4 + jj]  + gxr[512 + j]  + bias[4 + jj];
            float pi = sG[n][8 + jj]  + gxr[1024 + j] + bias[8 + jj];
            float ph = sG[n][12 + jj]                 + bias[12 + jj];
            float r = 1.f / (1.f + expf(-pr));
            float z = 1.f / (1.f + expf(-pz));
            float gg = tanhf(pi + r * ph);
            float hold = __bfloat162float(Hh[n * KD + j]) + __bfloat162float(Hl[n * KD + j]);
            float hn = (1.f - z) * gg + z * hold;
            __nv_bfloat16 hi, lo;
            split2(hn, hi, lo);
            size_t oidx = (size_t)(t + 1) * (NBAT * KD) + n * KD + j;
            g_H_hi[oidx] = hi;
            g_H_lo[oidx] = lo;
        }

        __syncthreads();
        if (tid == 0) {
            __threadfence();
            atomicAdd(&g_bar, 1u);
            unsigned target = 128u * (unsigned)(t + 1);
            while (*((volatile unsigned *)&g_bar) < target) { }
            __threadfence();
        }
        __syncthreads();
    }
}

// ---- out[n][t][p] = h_t @ Wp^T + b_p : grid (4,1024) x 256 threads ----
__global__ void __launch_bounds__(256) k_out(const float *__restrict__ bp,
                                             float *__restrict__ out) {
    int w = threadIdx.x >> 5, lane = threadIdx.x & 31;
    int g = lane >> 2, tg = lane & 3;
    int m0 = blockIdx.y * 64 + (w >> 1) * 16;   // m = t*64 + n
    int n0 = blockIdx.x * 64 + (w & 1) * 32;

    float acc[4][4];
#pragma unroll
    for (int i = 0; i < 4; i++)
#pragma unroll
        for (int q = 0; q < 4; q++) acc[i][q] = 0.f;

    // archive row for GEMM row m is m + 64 (slot t+1 holds h_t)
    const __nv_bfloat16 *a0h = g_H_hi + (size_t)(m0 + g + 64) * KD;
    const __nv_bfloat16 *a1h = g_H_hi + (size_t)(m0 + g + 8 + 64) * KD;
    const __nv_bfloat16 *a0l = g_H_lo + (size_t)(m0 + g + 64) * KD;
    const __nv_bfloat16 *a1l = g_H_lo + (size_t)(m0 + g + 8 + 64) * KD;

#pragma unroll 2
    for (int kc = 0; kc < KD; kc += 16) {
        unsigned ah[4], al[4];
        ah[0] = *(const unsigned *)(a0h + kc + tg * 2);
        ah[1] = *(const unsigned *)(a1h + kc + tg * 2);
        ah[2] = *(const unsigned *)(a0h + kc + tg * 2 + 8);
        ah[3] = *(const unsigned *)(a1h + kc + tg * 2 + 8);
        al[0] = *(const unsigned *)(a0l + kc + tg * 2);
        al[1] = *(const unsigned *)(a1l + kc + tg * 2);
        al[2] = *(const unsigned *)(a0l + kc + tg * 2 + 8);
        al[3] = *(const unsigned *)(a1l + kc + tg * 2 + 8);
#pragma unroll
        for (int nt = 0; nt < 4; nt++) {
            int col = n0 + nt * 8 + g;
            const __nv_bfloat16 *bh = g_Wp_hi + (size_t)col * KD + kc + tg * 2;
            const __nv_bfloat16 *bl = g_Wp_lo + (size_t)col * KD + kc + tg * 2;
            unsigned bhi[2] = { *(const unsigned *)bh, *(const unsigned *)(bh + 8) };
            unsigned blo[2] = { *(const unsigned *)bl, *(const unsigned *)(bl + 8) };
            mma_bf16(acc[nt], ah, bhi);
            mma_bf16(acc[nt], ah, blo);
            mma_bf16(acc[nt], al, bhi);
        }
    }

    int ma = m0 + g, mb = m0 + g + 8;
    // out[n][t][p], n = m & 63, t = m >> 6
    size_t ra = (size_t)(ma & 63) * (TT * 256) + (size_t)(ma >> 6) * 256;
    size_t rb = (size_t)(mb & 63) * (TT * 256) + (size_t)(mb >> 6) * 256;
#pragma unroll
    for (int nt = 0; nt < 4; nt++) {
        int col = n0 + nt * 8 + tg * 2;
        float b0 = bp[col], b1 = bp[col + 1];
        *(float2 *)(out + ra + col) = make_float2(acc[nt][0] + b0, acc[nt][1] + b1);
        *(float2 *)(out + rb + col) = make_float2(acc[nt][2] + b0, acc[nt][3] + b1);
    }
}

extern "C" void kernel_launch(void* const* d_in, const int* in_sizes, int n_in,
                              void* d_out, int out_size) {
    const float *X   = (const float *)d_in[0];
    // d_in[1] = text_lengths (unused: all == T, and reference ignores them)
    const float *Wih = (const float *)d_in[2];
    const float *Whh = (const float *)d_in[3];
    const float *bih = (const float *)d_in[4];
    const float *bhh = (const float *)d_in[5];
    const float *Wp  = (const float *)d_in[6];
    const float *bp  = (const float *)d_in[7];
    float *out = (float *)d_out;

    k_whp<<<(G3 * KD + 255) / 256, 256>>>(Wih, Wp);
    k_bpf<<<(G3 + 255) / 256, 256>>>(Wih, bp);
    int pack_n = 128 * 16 * KD + G3 * KD + 256 * KD;
    k_pack<<<(pack_n + 255) / 256, 256>>>(Wih, Whh, bih, bhh, Wp);
    k_splitx<<<(NBAT * TT * KD + 255) / 256, 256>>>(X);
    k_init<<<(NBAT * KD + 255) / 256, 256>>>();
    dim3 ggx(24, 1024);
    k_gx<<<ggx, 256>>>();
    k_rec<<<128, 128>>>();
    dim3 gout(4, 1024);
    k_out<<<gout, 256>>>(bp, out);
}

// round 12
// speedup vs baseline: 1.3070x; 1.3070x over previous
#include <cuda_runtime.h>
#include <cuda_bf16.h>
#include <math.h>

#define TT   1024
#define NBAT 64
#define KD   512
#define G3   1536
#define SHP  520          // smem h pitch (elements)

// ---- static device scratch ----
__device__ float          g_GX[(size_t)TT * NBAT * G3];
__device__ __nv_bfloat16  g_H_hi[(size_t)(TT + 1) * NBAT * KD];
__device__ __nv_bfloat16  g_H_lo[(size_t)(TT + 1) * NBAT * KD];
__device__ __nv_bfloat16  g_X_hi[(size_t)NBAT * TT * KD];
__device__ __nv_bfloat16  g_X_lo[(size_t)NBAT * TT * KD];
__device__ float          g_Whp[G3 * KD];
__device__ float          g_bpf[G3];
__device__ __nv_bfloat16  g_Mp_hi[128 * 16 * KD];
__device__ __nv_bfloat16  g_Mp_lo[128 * 16 * KD];
__device__ float          g_biasA[128 * 16];
__device__ float          g_bias0[128 * 16];
__device__ __nv_bfloat16  g_Wx_hi[G3 * KD];
__device__ __nv_bfloat16  g_Wx_lo[G3 * KD];
__device__ __nv_bfloat16  g_Wp_hi[256 * KD];
__device__ __nv_bfloat16  g_Wp_lo[256 * KD];
__device__ unsigned       g_bar;

__device__ __forceinline__ void split2(float v, __nv_bfloat16 &hi, __nv_bfloat16 &lo) {
    hi = __float2bfloat16(v);
    lo = __float2bfloat16(v - __bfloat162float(hi));
}

__device__ __forceinline__ void mma_bf16(float *d, const unsigned *a, const unsigned *b) {
    asm volatile(
        "mma.sync.aligned.m16n8k16.row.col.f32.bf16.bf16.f32 "
        "{%0,%1,%2,%3}, {%4,%5,%6,%7}, {%8,%9}, {%0,%1,%2,%3};\n"
        : "+f"(d[0]), "+f"(d[1]), "+f"(d[2]), "+f"(d[3])
        : "r"(a[0]), "r"(a[1]), "r"(a[2]), "r"(a[3]), "r"(b[0]), "r"(b[1]));
}

__device__ __forceinline__ unsigned smem_u32(const void *p) {
    return (unsigned)__cvta_generic_to_shared(p);
}

__device__ __forceinline__ void cp16(unsigned s, const void *g) {
    asm volatile("cp.async.cg.shared.global [%0], [%1], 16;\n" :: "r"(s), "l"(g));
}
#define CP_COMMIT() asm volatile("cp.async.commit_group;\n" ::: "memory")
#define CP_WAIT(n)  asm volatile("cp.async.wait_group %0;\n" :: "n"(n) : "memory")

__device__ __forceinline__ void ldsm4(unsigned *r, unsigned addr) {
    asm volatile("ldmatrix.sync.aligned.m8n8.x4.shared.b16 {%0,%1,%2,%3}, [%4];\n"
        : "=r"(r[0]), "=r"(r[1]), "=r"(r[2]), "=r"(r[3]) : "r"(addr));
}

// ---- prep 1: W_hp = W_pf @ W_p ; bpf = W_pf @ b_p ----
__global__ void k_prep1(const float *__restrict__ Wih, const float *__restrict__ Wp,
                        const float *__restrict__ bp) {
    int idx = blockIdx.x * blockDim.x + threadIdx.x;
    if (idx < G3 * KD) {
        int j = idx >> 9, k = idx & 511;
        const float *wrow = Wih + (size_t)j * 768 + 512;
        float acc = 0.f;
#pragma unroll 4
        for (int p = 0; p < 256; p++) acc += wrow[p] * Wp[p * KD + k];
        g_Whp[idx] = acc;
        return;
    }
    int j = idx - G3 * KD;
    if (j < G3) {
        const float *wrow = Wih + (size_t)j * 768 + 512;
        float acc = 0.f;
        for (int p = 0; p < 256; p++) acc += wrow[p] * bp[p];
        g_bpf[j] = acc;
    }
}

// ---- prep 2: pack Mp/biases, split Wx, split Wp, split X, init h0/bar ----
#define P0 (128 * 16 * KD)
#define P1 (G3 * KD)
#define P2 (256 * KD)
#define P3 ((size_t)NBAT * TT * KD)
#define P4 (NBAT * KD)
__global__ void k_prep2(const float *__restrict__ Wih, const float *__restrict__ Whh,
                        const float *__restrict__ bih, const float *__restrict__ bhh,
                        const float *__restrict__ Wp, const float *__restrict__ X) {
    size_t idx = (size_t)blockIdx.x * blockDim.x + threadIdx.x;

    if (idx < P0) {                                   // Mp + biases
        int k = (int)idx & 511;
        int c = ((int)idx >> 9) & 15;
        int b = (int)(idx >> 13);
        int gsel = c >> 2, jj = c & 3;
        int j = b * 4 + jj;
        float v;
        if (gsel == 0)      v = Whh[j * KD + k] + g_Whp[j * KD + k];
        else if (gsel == 1) v = Whh[(512 + j) * KD + k] + g_Whp[(512 + j) * KD + k];
        else if (gsel == 2) v = g_Whp[(1024 + j) * KD + k];
        else                v = Whh[(1024 + j) * KD + k];
        __nv_bfloat16 hi, lo;
        split2(v, hi, lo);
        g_Mp_hi[idx] = hi;
        g_Mp_lo[idx] = lo;
        if (k == 0) {
            float bb, b0;
            if (gsel == 0)      { b0 = bih[j] + bhh[j];             bb = b0 + g_bpf[j]; }
            else if (gsel == 1) { b0 = bih[512 + j] + bhh[512 + j]; bb = b0 + g_bpf[512 + j]; }
            else if (gsel == 2) { b0 = bih[1024 + j];               bb = b0 + g_bpf[1024 + j]; }
            else                { b0 = bhh[1024 + j];               bb = b0; }
            g_biasA[b * 16 + c] = bb;
            g_bias0[b * 16 + c] = b0;
        }
        return;
    }
    idx -= P0;

    if (idx < P1) {                                   // Wx split
        int j = (int)(idx >> 9), k = (int)idx & 511;
        __nv_bfloat16 hi, lo;
        split2(Wih[(size_t)j * 768 + k], hi, lo);
        g_Wx_hi[idx] = hi;
        g_Wx_lo[idx] = lo;
        return;
    }
    idx -= P1;

    if (idx < P2) {                                   // Wp split
        __nv_bfloat16 hi, lo;
        split2(Wp[idx], hi, lo);
        g_Wp_hi[idx] = hi;
        g_Wp_lo[idx] = lo;
        return;
    }
    idx -= P2;

    if (idx < P3) {                                   // X split
        __nv_bfloat16 hi, lo;
        split2(X[idx], hi, lo);
        g_X_hi[idx] = hi;
        g_X_lo[idx] = lo;
        return;
    }
    idx -= P3;

    if (idx < P4) {                                   // h slot 0 = 0
        g_H_hi[idx] = __float2bfloat16(0.f);
        g_H_lo[idx] = __float2bfloat16(0.f);
        return;
    }
    if (idx == P4) g_bar = 0u;
}

// ---- GX = X @ Wx^T : grid (24,1024) x 256 threads, 64x64 tiles ----
__global__ void __launch_bounds__(256) k_gx() {
    int w = threadIdx.x >> 5, lane = threadIdx.x & 31;
    int g = lane >> 2, tg = lane & 3;
    int m0 = blockIdx.y * 64 + (w >> 1) * 16;
    int n0 = blockIdx.x * 64 + (w & 1) * 32;

    float acc[4][4];
#pragma unroll
    for (int i = 0; i < 4; i++)
#pragma unroll
        for (int q = 0; q < 4; q++) acc[i][q] = 0.f;

    const __nv_bfloat16 *a0h = g_X_hi + (size_t)(m0 + g) * KD;
    const __nv_bfloat16 *a1h = g_X_hi + (size_t)(m0 + g + 8) * KD;
    const __nv_bfloat16 *a0l = g_X_lo + (size_t)(m0 + g) * KD;
    const __nv_bfloat16 *a1l = g_X_lo + (size_t)(m0 + g + 8) * KD;

#pragma unroll 2
    for (int kc = 0; kc < KD; kc += 16) {
        unsigned ah[4], al[4];
        ah[0] = *(const unsigned *)(a0h + kc + tg * 2);
        ah[1] = *(const unsigned *)(a1h + kc + tg * 2);
        ah[2] = *(const unsigned *)(a0h + kc + tg * 2 + 8);
        ah[3] = *(const unsigned *)(a1h + kc + tg * 2 + 8);
        al[0] = *(const unsigned *)(a0l + kc + tg * 2);
        al[1] = *(const unsigned *)(a1l + kc + tg * 2);
        al[2] = *(const unsigned *)(a0l + kc + tg * 2 + 8);
        al[3] = *(const unsigned *)(a1l + kc + tg * 2 + 8);
#pragma unroll
        for (int nt = 0; nt < 4; nt++) {
            int col = n0 + nt * 8 + g;
            const __nv_bfloat16 *bh = g_Wx_hi + (size_t)col * KD + kc + tg * 2;
            const __nv_bfloat16 *bl = g_Wx_lo + (size_t)col * KD + kc + tg * 2;
            unsigned bhi[2] = { *(const unsigned *)bh, *(const unsigned *)(bh + 8) };
            unsigned blo[2] = { *(const unsigned *)bl, *(const unsigned *)(bl + 8) };
            mma_bf16(acc[nt], ah, bhi);
            mma_bf16(acc[nt], ah, blo);
            mma_bf16(acc[nt], al, bhi);
        }
    }

    int ma = m0 + g, mb = m0 + g + 8;
    size_t ra = (size_t)((ma & 1023) * 64 + (ma >> 10)) * G3;
    size_t rb = (size_t)((mb & 1023) * 64 + (mb >> 10)) * G3;
#pragma unroll
    for (int nt = 0; nt < 4; nt++) {
        int col = n0 + nt * 8 + tg * 2;
        *(float2 *)(g_GX + ra + col) = make_float2(acc[nt][0], acc[nt][1]);
        *(float2 *)(g_GX + rb + col) = make_float2(acc[nt][2], acc[nt][3]);
    }
}

// ---- recurrence v2: 128 CTAs x 256 threads, smem-staged h + ldmatrix ----
// dynamic smem layout (bytes):
//   sWb   [0, 32768)            packed b-frags: [plane][nt][kc32][lane] uint2
//   sHhi  [32768, 99328)        64 x 520 bf16
//   sHlo  [99328, 165888)       64 x 520 bf16
//   sG    [165888, 170240)      64 x 17 float
//   sBias [170240, 170304) ; sBias0 [170304, 170368)
#define REC_SMEM 170368

__global__ void __launch_bounds__(256) k_rec() {
    extern __shared__ char smem[];
    uint2         *sWb  = (uint2 *)(smem);
    __nv_bfloat16 *sHhi = (__nv_bfloat16 *)(smem + 32768);
    __nv_bfloat16 *sHlo = (__nv_bfloat16 *)(smem + 99328);
    float         *sG   = (float *)(smem + 165888);
    float         *sBias  = (float *)(smem + 170240);
    float         *sBias0 = (float *)(smem + 170304);

    int b = blockIdx.x;
    int tid = threadIdx.x;
    int w = tid >> 5, lane = tid & 31;
    int g = lane >> 2, tg = lane & 3;

    // ---- one-time: pack b-frags into per-thread layout ----
    for (int idx = tid; idx < 4096; idx += 256) {
        int pl   = idx & 31;            // lane
        int kci  = (idx >> 5) & 31;
        int nt   = (idx >> 10) & 1;
        int plane= idx >> 11;
        int c  = nt * 8 + (pl >> 2);
        int k0 = kci * 16 + (pl & 3) * 2;
        const __nv_bfloat16 *row =
            (plane ? g_Mp_lo : g_Mp_hi) + (size_t)b * 8192 + c * 512;
        unsigned v0 = *(const unsigned *)(row + k0);
        unsigned v1 = *(const unsigned *)(row + k0 + 8);
        sWb[((plane * 2 + nt) * 32 + kci) * 32 + pl] = make_uint2(v0, v1);
    }
    if (tid < 16) {
        sBias[tid]  = g_biasA[b * 16 + tid];
        sBias0[tid] = g_bias0[b * 16 + tid];
    }
    __syncthreads();

    // MMA tile for this warp: m16n8, warp w -> m-tile (w>>1), n-tile (w&1)
    int m0 = (w >> 1) * 16;
    int nt = w & 1;
    int tile = lane >> 3;
    int lrow = m0 + ((tile & 1) << 3) + (lane & 7);
    int lcb  = (tile >> 1) * 8;
    unsigned aHiB = smem_u32(sHhi) + (unsigned)(lrow * SHP + lcb) * 2;
    unsigned aLoB = smem_u32(sHlo) + (unsigned)(lrow * SHP + lcb) * 2;
    const uint2 *wbH = sWb + (0 * 2 + nt) * 32 * 32 + lane;
    const uint2 *wbL = sWb + (1 * 2 + nt) * 32 * 32 + lane;

    unsigned sHhiU = smem_u32(sHhi);
    unsigned sHloU = smem_u32(sHlo);

    // gate-phase identity
    int gn = tid >> 2, gjj = tid & 3;
    int gj = b * 4 + gjj;

    for (int t = 0; t < TT; t++) {
        // prefetch GX gate operands (DRAM latency hides behind MMA phase)
        const float *GXt = g_GX + (size_t)t * (NBAT * G3);
        float gx_r = GXt[gn * G3 + gj];
        float gx_z = GXt[gn * G3 + 512 + gj];
        float gx_n = GXt[gn * G3 + 1024 + gj];

        const char *Hh = (const char *)g_H_hi + (size_t)t * 65536;
        const char *Hl = (const char *)g_H_lo + (size_t)t * 65536;

        // stage h into smem: two K-halves, 16 cp.async(16B) per thread per half
#pragma unroll
        for (int half = 0; half < 2; half++) {
#pragma unroll
            for (int it = 0; it < 16; it++) {
                int q = tid + it * 256;
                int plane = q >> 11;
                int r = q & 2047;
                int row = r >> 5, ch = r & 31;
                const char *gsrc = (plane ? Hl : Hh) + row * 1024 + half * 512 + ch * 16;
                unsigned sdst = (plane ? sHloU : sHhiU)
                              + (unsigned)(row * (SHP * 2) + half * 512 + ch * 16);
                cp16(sdst, gsrc);
            }
            CP_COMMIT();
        }

        float acc[4] = {0.f, 0.f, 0.f, 0.f};

        CP_WAIT(1);
        __syncthreads();
#pragma unroll 4
        for (int kk = 0; kk < 16; kk++) {
            int kc = kk * 16;
            unsigned ah[4], al[4];
            ldsm4(ah, aHiB + kc * 2);
            ldsm4(al, aLoB + kc * 2);
            uint2 bh = wbH[(kc >> 4) * 32];
            uint2 bl = wbL[(kc >> 4) * 32];
            mma_bf16(acc, ah, (const unsigned *)&bh);
            mma_bf16(acc, ah, (const unsigned *)&bl);
            mma_bf16(acc, al, (const unsigned *)&bh);
        }

        CP_WAIT(0);
        __syncthreads();
#pragma unroll 4
        for (int kk = 16; kk < 32; kk++) {
            int kc = kk * 16;
            unsigned ah[4], al[4];
            ldsm4(ah, aHiB + kc * 2);
            ldsm4(al, aLoB + kc * 2);
            uint2 bh = wbH[(kc >> 4) * 32];
            uint2 bl = wbL[(kc >> 4) * 32];
            mma_bf16(acc, ah, (const unsigned *)&bh);
            mma_bf16(acc, ah, (const unsigned *)&bl);
            mma_bf16(acc, al, (const unsigned *)&bh);
        }

        // epilogue: acc -> sG
        {
            int c = nt * 8 + tg * 2;
            sG[(m0 + g) * 17 + c]     = acc[0];
            sG[(m0 + g) * 17 + c + 1] = acc[1];
            sG[(m0 + g + 8) * 17 + c]     = acc[2];
            sG[(m0 + g + 8) * 17 + c + 1] = acc[3];
        }
        __syncthreads();

        // gates: one (n, jj) item per thread
        {
            const float *bias = (t == 0) ? sBias0 : sBias;
            float pr = sG[gn * 17 + gjj]      + gx_r + bias[gjj];
            float pz = sG[gn * 17 + 4 + gjj]  + gx_z + bias[4 + gjj];
            float pi = sG[gn * 17 + 8 + gjj]  + gx_n + bias[8 + gjj];
            float ph = sG[gn * 17 + 12 + gjj]        + bias[12 + gjj];
            float r = 1.f / (1.f + expf(-pr));
            float z = 1.f / (1.f + expf(-pz));
            float gg = tanhf(pi + r * ph);
            float hold = __bfloat162float(sHhi[gn * SHP + gj])
                       + __bfloat162float(sHlo[gn * SHP + gj]);
            float hn = (1.f - z) * gg + z * hold;
            __nv_bfloat16 hi, lo;
            split2(hn, hi, lo);
            size_t oidx = (size_t)(t + 1) * (NBAT * KD) + gn * KD + gj;
            g_H_hi[oidx] = hi;
            g_H_lo[oidx] = lo;
        }

        __threadfence();
        __syncthreads();
        if (tid == 0) {
            atomicAdd(&g_bar, 1u);
            unsigned target = 128u * (unsigned)(t + 1);
            while (*((volatile unsigned *)&g_bar) < target) { }
            __threadfence();
        }
        __syncthreads();
    }
}

// ---- out[n][t][p] = h_t @ Wp^T + b_p : grid (4,1024) x 256 threads ----
__global__ void __launch_bounds__(256) k_out(const float *__restrict__ bp,
                                             float *__restrict__ out) {
    int w = threadIdx.x >> 5, lane = threadIdx.x & 31;
    int g = lane >> 2, tg = lane & 3;
    int m0 = blockIdx.y * 64 + (w >> 1) * 16;   // m = t*64 + n
    int n0 = blockIdx.x * 64 + (w & 1) * 32;

    float acc[4][4];
#pragma unroll
    for (int i = 0; i < 4; i++)
#pragma unroll
        for (int q = 0; q < 4; q++) acc[i][q] = 0.f;

    const __nv_bfloat16 *a0h = g_H_hi + (size_t)(m0 + g + 64) * KD;
    const __nv_bfloat16 *a1h = g_H_hi + (size_t)(m0 + g + 8 + 64) * KD;
    const __nv_bfloat16 *a0l = g_H_lo + (size_t)(m0 + g + 64) * KD;
    const __nv_bfloat16 *a1l = g_H_lo + (size_t)(m0 + g + 8 + 64) * KD;

#pragma unroll 2
    for (int kc = 0; kc < KD; kc += 16) {
        unsigned ah[4], al[4];
        ah[0] = *(const unsigned *)(a0h + kc + tg * 2);
        ah[1] = *(const unsigned *)(a1h + kc + tg * 2);
        ah[2] = *(const unsigned *)(a0h + kc + tg * 2 + 8);
        ah[3] = *(const unsigned *)(a1h + kc + tg * 2 + 8);
        al[0] = *(const unsigned *)(a0l + kc + tg * 2);
        al[1] = *(const unsigned *)(a1l + kc + tg * 2);
        al[2] = *(const unsigned *)(a0l + kc + tg * 2 + 8);
        al[3] = *(const unsigned *)(a1l + kc + tg * 2 + 8);
#pragma unroll
        for (int nt = 0; nt < 4; nt++) {
            int col = n0 + nt * 8 + g;
            const __nv_bfloat16 *bh = g_Wp_hi + (size_t)col * KD + kc + tg * 2;
            const __nv_bfloat16 *bl = g_Wp_lo + (size_t)col * KD + kc + tg * 2;
            unsigned bhi[2] = { *(const unsigned *)bh, *(const unsigned *)(bh + 8) };
            unsigned blo[2] = { *(const unsigned *)bl, *(const unsigned *)(bl + 8) };
            mma_bf16(acc[nt], ah, bhi);
            mma_bf16(acc[nt], ah, blo);
            mma_bf16(acc[nt], al, bhi);
        }
    }

    int ma = m0 + g, mb = m0 + g + 8;
    size_t ra = (size_t)(ma & 63) * (TT * 256) + (size_t)(ma >> 6) * 256;
    size_t rb = (size_t)(mb & 63) * (TT * 256) + (size_t)(mb >> 6) * 256;
#pragma unroll
    for (int nt = 0; nt < 4; nt++) {
        int col = n0 + nt * 8 + tg * 2;
        float b0 = bp[col], b1 = bp[col + 1];
        *(float2 *)(out + ra + col) = make_float2(acc[nt][0] + b0, acc[nt][1] + b1);
        *(float2 *)(out + rb + col) = make_float2(acc[nt][2] + b0, acc[nt][3] + b1);
    }
}

extern "C" void kernel_launch(void* const* d_in, const int* in_sizes, int n_in,
                              void* d_out, int out_size) {
    const float *X   = (const float *)d_in[0];
    // d_in[1] = text_lengths (all == T; reference ignores them)
    const float *Wih = (const float *)d_in[2];
    const float *Whh = (const float *)d_in[3];
    const float *bih = (const float *)d_in[4];
    const float *bhh = (const float *)d_in[5];
    const float *Wp  = (const float *)d_in[6];
    const float *bp  = (const float *)d_in[7];
    float *out = (float *)d_out;

    static int smem_set = 0;
    if (!smem_set) {
        cudaFuncSetAttribute(k_rec, cudaFuncAttributeMaxDynamicSharedMemorySize, REC_SMEM);
        smem_set = 1;
    }

    int n1 = G3 * KD + G3;
    k_prep1<<<(n1 + 255) / 256, 256>>>(Wih, Wp, bp);

    size_t n2 = (size_t)P0 + P1 + P2 + P3 + P4 + 1;
    k_prep2<<<(unsigned)((n2 + 255) / 256), 256>>>(Wih, Whh, bih, bhh, Wp, X);

    dim3 ggx(24, 1024);
    k_gx<<<ggx, 256>>>();

    k_rec<<<128, 256, REC_SMEM>>>();

    dim3 gout(4, 1024);
    k_out<<<gout, 256>>>(bp, out);
}

// round 13
// speedup vs baseline: 1.3924x; 1.0653x over previous
#include <cuda_runtime.h>
#include <cuda_bf16.h>
#include <math.h>

#define TT   1024
#define NBAT 64
#define KD   512
#define G3   1536
#define SHP  520          // smem h pitch (elements)

// ---- static device scratch ----
__device__ float          g_GX[(size_t)TT * NBAT * G3];
__device__ __nv_bfloat16  g_H_hi[(size_t)(TT + 1) * NBAT * KD];
__device__ __nv_bfloat16  g_H_lo[(size_t)(TT + 1) * NBAT * KD];
__device__ __nv_bfloat16  g_X_hi[(size_t)NBAT * TT * KD];
__device__ __nv_bfloat16  g_X_lo[(size_t)NBAT * TT * KD];
__device__ float          g_Whp[G3 * KD];
__device__ float          g_bpf[G3];
__device__ __nv_bfloat16  g_Mp_hi[128 * 16 * KD];
__device__ __nv_bfloat16  g_Mp_lo[128 * 16 * KD];
__device__ float          g_biasA[128 * 16];
__device__ float          g_bias0[128 * 16];
__device__ __nv_bfloat16  g_Wx_hi[G3 * KD];
__device__ __nv_bfloat16  g_Wx_lo[G3 * KD];
__device__ __nv_bfloat16  g_Wp_hi[256 * KD];
__device__ __nv_bfloat16  g_Wp_lo[256 * KD];
__device__ unsigned       g_cnt[TT];    // per-step barrier counters (self-cleaning)
__device__ unsigned       g_fin;        // final cleanup round

__device__ __forceinline__ void split2(float v, __nv_bfloat16 &hi, __nv_bfloat16 &lo) {
    hi = __float2bfloat16(v);
    lo = __float2bfloat16(v - __bfloat162float(hi));
}

__device__ __forceinline__ void mma_bf16(float *d, const unsigned *a, const unsigned *b) {
    asm volatile(
        "mma.sync.aligned.m16n8k16.row.col.f32.bf16.bf16.f32 "
        "{%0,%1,%2,%3}, {%4,%5,%6,%7}, {%8,%9}, {%0,%1,%2,%3};\n"
        : "+f"(d[0]), "+f"(d[1]), "+f"(d[2]), "+f"(d[3])
        : "r"(a[0]), "r"(a[1]), "r"(a[2]), "r"(a[3]), "r"(b[0]), "r"(b[1]));
}

__device__ __forceinline__ unsigned smem_u32(const void *p) {
    return (unsigned)__cvta_generic_to_shared(p);
}

__device__ __forceinline__ void cp16(unsigned s, const void *g) {
    asm volatile("cp.async.cg.shared.global [%0], [%1], 16;\n" :: "r"(s), "l"(g));
}
#define CP_COMMIT() asm volatile("cp.async.commit_group;\n" ::: "memory")
#define CP_WAIT(n)  asm volatile("cp.async.wait_group %0;\n" :: "n"(n) : "memory")

__device__ __forceinline__ void ldsm4(unsigned *r, unsigned addr) {
    asm volatile("ldmatrix.sync.aligned.m8n8.x4.shared.b16 {%0,%1,%2,%3}, [%4];\n"
        : "=r"(r[0]), "=r"(r[1]), "=r"(r[2]), "=r"(r[3]) : "r"(addr));
}

__device__ __forceinline__ unsigned atom_add_gpu(unsigned *p, unsigned v) {
    unsigned old;
    asm volatile("atom.relaxed.gpu.add.u32 %0, [%1], %2;\n"
                 : "=r"(old) : "l"(p), "r"(v) : "memory");
    return old;
}

__device__ __forceinline__ unsigned ld_acq_gpu(const unsigned *p) {
    unsigned v;
    asm volatile("ld.acquire.gpu.u32 %0, [%1];\n" : "=r"(v) : "l"(p) : "memory");
    return v;
}

// ---- prep 1: W_hp = W_pf @ W_p ; bpf = W_pf @ b_p ----
__global__ void k_prep1(const float *__restrict__ Wih, const float *__restrict__ Wp,
                        const float *__restrict__ bp) {
    int idx = blockIdx.x * blockDim.x + threadIdx.x;
    if (idx < G3 * KD) {
        int j = idx >> 9, k = idx & 511;
        const float *wrow = Wih + (size_t)j * 768 + 512;
        float acc = 0.f;
#pragma unroll 4
        for (int p = 0; p < 256; p++) acc += wrow[p] * Wp[p * KD + k];
        g_Whp[idx] = acc;
        return;
    }
    int j = idx - G3 * KD;
    if (j < G3) {
        const float *wrow = Wih + (size_t)j * 768 + 512;
        float acc = 0.f;
        for (int p = 0; p < 256; p++) acc += wrow[p] * bp[p];
        g_bpf[j] = acc;
    }
}

// ---- prep 2: pack Mp/biases, split Wx, split Wp, split X, init h0/barriers ----
#define P0 (128 * 16 * KD)
#define P1 (G3 * KD)
#define P2 (256 * KD)
#define P3 ((size_t)NBAT * TT * KD)
#define P4 (NBAT * KD)
__global__ void k_prep2(const float *__restrict__ Wih, const float *__restrict__ Whh,
                        const float *__restrict__ bih, const float *__restrict__ bhh,
                        const float *__restrict__ Wp, const float *__restrict__ X) {
    size_t idx = (size_t)blockIdx.x * blockDim.x + threadIdx.x;

    if (idx < P0) {                                   // Mp + biases
        int k = (int)idx & 511;
        int c = ((int)idx >> 9) & 15;
        int b = (int)(idx >> 13);
        int gsel = c >> 2, jj = c & 3;
        int j = b * 4 + jj;
        float v;
        if (gsel == 0)      v = Whh[j * KD + k] + g_Whp[j * KD + k];
        else if (gsel == 1) v = Whh[(512 + j) * KD + k] + g_Whp[(512 + j) * KD + k];
        else if (gsel == 2) v = g_Whp[(1024 + j) * KD + k];
        else                v = Whh[(1024 + j) * KD + k];
        __nv_bfloat16 hi, lo;
        split2(v, hi, lo);
        g_Mp_hi[idx] = hi;
        g_Mp_lo[idx] = lo;
        if (k == 0) {
            float bb, b0;
            if (gsel == 0)      { b0 = bih[j] + bhh[j];             bb = b0 + g_bpf[j]; }
            else if (gsel == 1) { b0 = bih[512 + j] + bhh[512 + j]; bb = b0 + g_bpf[512 + j]; }
            else if (gsel == 2) { b0 = bih[1024 + j];               bb = b0 + g_bpf[1024 + j]; }
            else                { b0 = bhh[1024 + j];               bb = b0; }
            g_biasA[b * 16 + c] = bb;
            g_bias0[b * 16 + c] = b0;
        }
        return;
    }
    idx -= P0;

    if (idx < P1) {                                   // Wx split
        int j = (int)(idx >> 9), k = (int)idx & 511;
        __nv_bfloat16 hi, lo;
        split2(Wih[(size_t)j * 768 + k], hi, lo);
        g_Wx_hi[idx] = hi;
        g_Wx_lo[idx] = lo;
        return;
    }
    idx -= P1;

    if (idx < P2) {                                   // Wp split
        __nv_bfloat16 hi, lo;
        split2(Wp[idx], hi, lo);
        g_Wp_hi[idx] = hi;
        g_Wp_lo[idx] = lo;
        return;
    }
    idx -= P2;

    if (idx < P3) {                                   // X split
        __nv_bfloat16 hi, lo;
        split2(X[idx], hi, lo);
        g_X_hi[idx] = hi;
        g_X_lo[idx] = lo;
        return;
    }
    idx -= P3;

    if (idx < P4) {                                   // h slot 0 = 0
        g_H_hi[idx] = __float2bfloat16(0.f);
        g_H_lo[idx] = __float2bfloat16(0.f);
        return;
    }
    idx -= P4;
    if (idx < TT) { g_cnt[idx] = 0u; return; }        // barrier counters
    if (idx == TT) g_fin = 0u;
}

// ---- GX = X @ Wx^T : grid (24,1024) x 256 threads, 64x64 tiles ----
__global__ void __launch_bounds__(256) k_gx() {
    int w = threadIdx.x >> 5, lane = threadIdx.x & 31;
    int g = lane >> 2, tg = lane & 3;
    int m0 = blockIdx.y * 64 + (w >> 1) * 16;
    int n0 = blockIdx.x * 64 + (w & 1) * 32;

    float acc[4][4];
#pragma unroll
    for (int i = 0; i < 4; i++)
#pragma unroll
        for (int q = 0; q < 4; q++) acc[i][q] = 0.f;

    const __nv_bfloat16 *a0h = g_X_hi + (size_t)(m0 + g) * KD;
    const __nv_bfloat16 *a1h = g_X_hi + (size_t)(m0 + g + 8) * KD;
    const __nv_bfloat16 *a0l = g_X_lo + (size_t)(m0 + g) * KD;
    const __nv_bfloat16 *a1l = g_X_lo + (size_t)(m0 + g + 8) * KD;

#pragma unroll 2
    for (int kc = 0; kc < KD; kc += 16) {
        unsigned ah[4], al[4];
        ah[0] = *(const unsigned *)(a0h + kc + tg * 2);
        ah[1] = *(const unsigned *)(a1h + kc + tg * 2);
        ah[2] = *(const unsigned *)(a0h + kc + tg * 2 + 8);
        ah[3] = *(const unsigned *)(a1h + kc + tg * 2 + 8);
        al[0] = *(const unsigned *)(a0l + kc + tg * 2);
        al[1] = *(const unsigned *)(a1l + kc + tg * 2);
        al[2] = *(const unsigned *)(a0l + kc + tg * 2 + 8);
        al[3] = *(const unsigned *)(a1l + kc + tg * 2 + 8);
#pragma unroll
        for (int nt = 0; nt < 4; nt++) {
            int col = n0 + nt * 8 + g;
            const __nv_bfloat16 *bh = g_Wx_hi + (size_t)col * KD + kc + tg * 2;
            const __nv_bfloat16 *bl = g_Wx_lo + (size_t)col * KD + kc + tg * 2;
            unsigned bhi[2] = { *(const unsigned *)bh, *(const unsigned *)(bh + 8) };
            unsigned blo[2] = { *(const unsigned *)bl, *(const unsigned *)(bl + 8) };
            mma_bf16(acc[nt], ah, bhi);
            mma_bf16(acc[nt], ah, blo);
            mma_bf16(acc[nt], al, bhi);
        }
    }

    int ma = m0 + g, mb = m0 + g + 8;
    size_t ra = (size_t)((ma & 1023) * 64 + (ma >> 10)) * G3;
    size_t rb = (size_t)((mb & 1023) * 64 + (mb >> 10)) * G3;
#pragma unroll
    for (int nt = 0; nt < 4; nt++) {
        int col = n0 + nt * 8 + tg * 2;
        *(float2 *)(g_GX + ra + col) = make_float2(acc[nt][0], acc[nt][1]);
        *(float2 *)(g_GX + rb + col) = make_float2(acc[nt][2], acc[nt][3]);
    }
}

// ---- recurrence v3: 128 CTAs x 256 threads ----
// smem layout (bytes):
//   sWb   [0, 32768)       packed b-frags: [plane][nt][kc32][lane] uint2
//   sHhi  [32768, 99328)   64 x 520 bf16
//   sHlo  [99328, 165888)  64 x 520 bf16
//   sG    [165888, 170240) 64 x 17 float
//   sBias [170240, 170304) ; sBias0 [170304, 170368)
#define REC_SMEM 170368

__global__ void __launch_bounds__(256) k_rec() {
    extern __shared__ char smem[];
    uint2         *sWb  = (uint2 *)(smem);
    __nv_bfloat16 *sHhi = (__nv_bfloat16 *)(smem + 32768);
    __nv_bfloat16 *sHlo = (__nv_bfloat16 *)(smem + 99328);
    float         *sG   = (float *)(smem + 165888);
    float         *sBias  = (float *)(smem + 170240);
    float         *sBias0 = (float *)(smem + 170304);

    int b = blockIdx.x;
    int tid = threadIdx.x;
    int w = tid >> 5, lane = tid & 31;
    int g = lane >> 2, tg = lane & 3;

    // one-time: pack b-frags into per-thread layout
    for (int idx = tid; idx < 4096; idx += 256) {
        int pl   = idx & 31;
        int kci  = (idx >> 5) & 31;
        int nt   = (idx >> 10) & 1;
        int plane= idx >> 11;
        int c  = nt * 8 + (pl >> 2);
        int k0 = kci * 16 + (pl & 3) * 2;
        const __nv_bfloat16 *row =
            (plane ? g_Mp_lo : g_Mp_hi) + (size_t)b * 8192 + c * 512;
        unsigned v0 = *(const unsigned *)(row + k0);
        unsigned v1 = *(const unsigned *)(row + k0 + 8);
        sWb[((plane * 2 + nt) * 32 + kci) * 32 + pl] = make_uint2(v0, v1);
    }
    if (tid < 16) {
        sBias[tid]  = g_biasA[b * 16 + tid];
        sBias0[tid] = g_bias0[b * 16 + tid];
    }
    __syncthreads();

    int m0 = (w >> 1) * 16;
    int nt = w & 1;
    int tile = lane >> 3;
    int lrow = m0 + ((tile & 1) << 3) + (lane & 7);
    int lcb  = (tile >> 1) * 8;
    unsigned aHiB = smem_u32(sHhi) + (unsigned)(lrow * SHP + lcb) * 2;
    unsigned aLoB = smem_u32(sHlo) + (unsigned)(lrow * SHP + lcb) * 2;
    const uint2 *wbH = sWb + (0 * 2 + nt) * 32 * 32 + lane;
    const uint2 *wbL = sWb + (1 * 2 + nt) * 32 * 32 + lane;

    unsigned sHhiU = smem_u32(sHhi);
    unsigned sHloU = smem_u32(sHlo);

    int gn = tid >> 2, gjj = tid & 3;
    int gj = b * 4 + gjj;

    for (int t = 0; t < TT; t++) {
        // prefetch GX gate operands
        const float *GXt = g_GX + (size_t)t * (NBAT * G3);
        float gx_r = GXt[gn * G3 + gj];
        float gx_z = GXt[gn * G3 + 512 + gj];
        float gx_n = GXt[gn * G3 + 1024 + gj];

        const char *Hh = (const char *)g_H_hi + (size_t)t * 65536;
        const char *Hl = (const char *)g_H_lo + (size_t)t * 65536;

        // stage h: two K-halves of cp.async(16B)
#pragma unroll
        for (int half = 0; half < 2; half++) {
#pragma unroll
            for (int it = 0; it < 16; it++) {
                int q = tid + it * 256;
                int plane = q >> 11;
                int r = q & 2047;
                int row = r >> 5, ch = r & 31;
                const char *gsrc = (plane ? Hl : Hh) + row * 1024 + half * 512 + ch * 16;
                unsigned sdst = (plane ? sHloU : sHhiU)
                              + (unsigned)(row * (SHP * 2) + half * 512 + ch * 16);
                cp16(sdst, gsrc);
            }
            CP_COMMIT();
        }

        float accA[4] = {0.f, 0.f, 0.f, 0.f};   // hi*hi
        float accB[4] = {0.f, 0.f, 0.f, 0.f};   // hi*lo
        float accC[4] = {0.f, 0.f, 0.f, 0.f};   // lo*hi

        unsigned ah[2][4], al[2][4];

        CP_WAIT(1);
        __syncthreads();
        ldsm4(ah[0], aHiB);
        ldsm4(al[0], aLoB);
#pragma unroll
        for (int kk = 0; kk < 16; kk++) {
            int p = kk & 1, pn = p ^ 1;
            if (kk < 15) {
                ldsm4(ah[pn], aHiB + (kk + 1) * 32);
                ldsm4(al[pn], aLoB + (kk + 1) * 32);
            }
            uint2 bh = wbH[kk * 32];
            uint2 bl = wbL[kk * 32];
            mma_bf16(accA, ah[p], (const unsigned *)&bh);
            mma_bf16(accB, ah[p], (const unsigned *)&bl);
            mma_bf16(accC, al[p], (const unsigned *)&bh);
        }

        CP_WAIT(0);
        __syncthreads();
        ldsm4(ah[0], aHiB + 16 * 32);
        ldsm4(al[0], aLoB + 16 * 32);
#pragma unroll
        for (int kk = 16; kk < 32; kk++) {
            int p = kk & 1, pn = p ^ 1;
            if (kk < 31) {
                ldsm4(ah[pn], aHiB + (kk + 1) * 32);
                ldsm4(al[pn], aLoB + (kk + 1) * 32);
            }
            uint2 bh = wbH[kk * 32];
            uint2 bl = wbL[kk * 32];
            mma_bf16(accA, ah[p], (const unsigned *)&bh);
            mma_bf16(accB, ah[p], (const unsigned *)&bl);
            mma_bf16(accC, al[p], (const unsigned *)&bh);
        }

        // epilogue: acc -> sG
        {
            int c = nt * 8 + tg * 2;
            sG[(m0 + g) * 17 + c]         = accA[0] + accB[0] + accC[0];
            sG[(m0 + g) * 17 + c + 1]     = accA[1] + accB[1] + accC[1];
            sG[(m0 + g + 8) * 17 + c]     = accA[2] + accB[2] + accC[2];
            sG[(m0 + g + 8) * 17 + c + 1] = accA[3] + accB[3] + accC[3];
        }
        __syncthreads();

        // gates
        {
            const float *bias = (t == 0) ? sBias0 : sBias;
            float pr = sG[gn * 17 + gjj]      + gx_r + bias[gjj];
            float pz = sG[gn * 17 + 4 + gjj]  + gx_z + bias[4 + gjj];
            float pi = sG[gn * 17 + 8 + gjj]  + gx_n + bias[8 + gjj];
            float ph = sG[gn * 17 + 12 + gjj]        + bias[12 + gjj];
            float r = 1.f / (1.f + __expf(-pr));
            float z = 1.f / (1.f + __expf(-pz));
            float ex = __expf(2.f * (pi + r * ph));
            float gg = __fdividef(ex - 1.f, ex + 1.f);
            float hold = __bfloat162float(sHhi[gn * SHP + gj])
                       + __bfloat162float(sHlo[gn * SHP + gj]);
            float hn = (1.f - z) * gg + z * hold;
            __nv_bfloat16 hi, lo;
            split2(hn, hi, lo);
            size_t oidx = (size_t)(t + 1) * (NBAT * KD) + gn * KD + gj;
            g_H_hi[oidx] = hi;
            g_H_lo[oidx] = lo;
        }

        // lightweight grid barrier: CG pattern, per-step counter, self-cleaning
        __syncthreads();
        if (tid == 0) {
            asm volatile("fence.acq_rel.gpu;\n" ::: "memory");
            unsigned old = atom_add_gpu(&g_cnt[t], 1u);
            if (old == 127u && t > 0) g_cnt[t - 1] = 0u;   // all passed barrier t-1
            while (ld_acq_gpu(&g_cnt[t]) < 128u) { }
        }
        __syncthreads();
    }

    // final cleanup round (keeps kernel replay-idempotent)
    if (tid == 0) {
        unsigned old = atom_add_gpu(&g_fin, 1u);
        if (old == 127u) {
            g_cnt[TT - 1] = 0u;
            g_fin = 0u;
        }
    }
}

// ---- out[n][t][p] = h_t @ Wp^T + b_p : grid (4,1024) x 256 threads ----
__global__ void __launch_bounds__(256) k_out(const float *__restrict__ bp,
                                             float *__restrict__ out) {
    int w = threadIdx.x >> 5, lane = threadIdx.x & 31;
    int g = lane >> 2, tg = lane & 3;
    int m0 = blockIdx.y * 64 + (w >> 1) * 16;   // m = t*64 + n
    int n0 = blockIdx.x * 64 + (w & 1) * 32;

    float acc[4][4];
#pragma unroll
    for (int i = 0; i < 4; i++)
#pragma unroll
        for (int q = 0; q < 4; q++) acc[i][q] = 0.f;

    const __nv_bfloat16 *a0h = g_H_hi + (size_t)(m0 + g + 64) * KD;
    const __nv_bfloat16 *a1h = g_H_hi + (size_t)(m0 + g + 8 + 64) * KD;
    const __nv_bfloat16 *a0l = g_H_lo + (size_t)(m0 + g + 64) * KD;
    const __nv_bfloat16 *a1l = g_H_lo + (size_t)(m0 + g + 8 + 64) * KD;

#pragma unroll 2
    for (int kc = 0; kc < KD; kc += 16) {
        unsigned ah[4], al[4];
        ah[0] = *(const unsigned *)(a0h + kc + tg * 2);
        ah[1] = *(const unsigned *)(a1h + kc + tg * 2);
        ah[2] = *(const unsigned *)(a0h + kc + tg * 2 + 8);
        ah[3] = *(const unsigned *)(a1h + kc + tg * 2 + 8);
        al[0] = *(const unsigned *)(a0l + kc + tg * 2);
        al[1] = *(const unsigned *)(a1l + kc + tg * 2);
        al[2] = *(const unsigned *)(a0l + kc + tg * 2 + 8);
        al[3] = *(const unsigned *)(a1l + kc + tg * 2 + 8);
#pragma unroll
        for (int nt = 0; nt < 4; nt++) {
            int col = n0 + nt * 8 + g;
            const __nv_bfloat16 *bh = g_Wp_hi + (size_t)col * KD + kc + tg * 2;
            const __nv_bfloat16 *bl = g_Wp_lo + (size_t)col * KD + kc + tg * 2;
            unsigned bhi[2] = { *(const unsigned *)bh, *(const unsigned *)(bh + 8) };
            unsigned blo[2] = { *(const unsigned *)bl, *(const unsigned *)(bl + 8) };
            mma_bf16(acc[nt], ah, bhi);
            mma_bf16(acc[nt], ah, blo);
            mma_bf16(acc[nt], al, bhi);
        }
    }

    int ma = m0 + g, mb = m0 + g + 8;
    size_t ra = (size_t)(ma & 63) * (TT * 256) + (size_t)(ma >> 6) * 256;
    size_t rb = (size_t)(mb & 63) * (TT * 256) + (size_t)(mb >> 6) * 256;
#pragma unroll
    for (int nt = 0; nt < 4; nt++) {
        int col = n0 + nt * 8 + tg * 2;
        float b0 = bp[col], b1 = bp[col + 1];
        *(float2 *)(out + ra + col) = make_float2(acc[nt][0] + b0, acc[nt][1] + b1);
        *(float2 *)(out + rb + col) = make_float2(acc[nt][2] + b0, acc[nt][3] + b1);
    }
}

extern "C" void kernel_launch(void* const* d_in, const int* in_sizes, int n_in,
                              void* d_out, int out_size) {
    const float *X   = (const float *)d_in[0];
    // d_in[1] = text_lengths (all == T; reference ignores them)
    const float *Wih = (const float *)d_in[2];
    const float *Whh = (const float *)d_in[3];
    const float *bih = (const float *)d_in[4];
    const float *bhh = (const float *)d_in[5];
    const float *Wp  = (const float *)d_in[6];
    const float *bp  = (const float *)d_in[7];
    float *out = (float *)d_out;

    static int smem_set = 0;
    if (!smem_set) {
        cudaFuncSetAttribute(k_rec, cudaFuncAttributeMaxDynamicSharedMemorySize, REC_SMEM);
        smem_set = 1;
    }

    int n1 = G3 * KD + G3;
    k_prep1<<<(n1 + 255) / 256, 256>>>(Wih, Wp, bp);

    size_t n2 = (size_t)P0 + P1 + P2 + P3 + P4 + TT + 1;
    k_prep2<<<(unsigned)((n2 + 255) / 256), 256>>>(Wih, Whh, bih, bhh, Wp, X);

    dim3 ggx(24, 1024);
    k_gx<<<ggx, 256>>>();

    k_rec<<<128, 256, REC_SMEM>>>();

    dim3 gout(4, 1024);
    k_out<<<gout, 256>>>(bp, out);
}